// round 7
// baseline (speedup 1.0000x reference)
#include <cuda_runtime.h>
#include <cuda_bf16.h>
#include <math.h>

// Problem constants
#define TT     1024
#define DD     4
#define PP     8
#define DPW    32                    // D*P
#define SS     256                   // N * N_SAMPLE
#define LT     8                     // timesteps per chunk
#define NCH    32                    // chunks per block
#define BLK_T  256                   // timesteps per block (NCH*LT)
#define BPS    4                     // blocks per sample (TT/BLK_T)
#define NBLK   (SS*BPS)              // 1024 blocks
#define TBL    (TT*DPW)              // 32768 table elements
#define SZ     ((size_t)SS*TT*DPW)   // 8388608 elements per output tensor
#define HLOG2PI 0.91893853320467274178f

// Precomputed tables + lookback state (allocation-free scratch)
__device__ float g_mean[TBL];
__device__ float g_sw[TBL];
__device__ float g_amul[TT*DD];          // sigmoid(a_raw[t-1,d]), amul[0,*]=0
__device__ volatile int g_flag[NBLK];    // lookback ready flags
__device__ float g_P[NBLK][DPW];         // inclusive carry per block

// ---------------------------------------------------------------------------
// K0: precompute tables AND reset lookback flags (runs first, same stream).
// ---------------------------------------------------------------------------
__global__ void arma_precompute(const float* __restrict__ m,
                                const float* __restrict__ s_raw,
                                const float* __restrict__ a_raw,
                                const int*   __restrict__ dim_idx)
{
    int idx = blockIdx.x * blockDim.x + threadIdx.x;
    if (idx >= TBL) return;
    if (idx < NBLK) g_flag[idx] = 0;     // reset lookback flags each launch

    int t  = idx >> 5;
    int dp = idx & 31;
    int dd = dp >> 3;
    int p  = dp & 7;
    int src = dim_idx[dd];

    float am = 0.0f;
    if (t > 0) {
        float x = a_raw[(t - 1) * DD + src];
        am = 1.0f / (1.0f + __expf(-x));
    }

    float sv = s_raw[t * DPW + src * PP + p];
    float sw = (sv > 20.0f) ? sv : __logf(1.0f + __expf(sv));   // softplus
    float mn = (1.0f - am) * m[t * DPW + src * PP + p];

    g_mean[idx] = mn;
    g_sw[idx]   = sw;
    if (p == 0) g_amul[t * DD + dd] = am;
}

// ---------------------------------------------------------------------------
// Main kernel: 1024 blocks x 256 threads. Block (s, blk) covers timesteps
// [blk*256, blk*256+256) of sample s. Small blocks => 4-5 blocks/SM so the
// load/compute/scan/store phases of co-resident blocks overlap.
// Cross-block carries resolved by decoupled lookback over g_P/g_flag
// (predecessor bid is smaller => scheduled no later => no deadlock).
// ---------------------------------------------------------------------------
__global__ void __launch_bounds__(256)
arma_main(const float4* __restrict__ noise4,
          float4* __restrict__ param4,
          float4* __restrict__ lp4,
          int write_lp)
{
    const int bid  = blockIdx.x;
    const int s    = bid >> 2;
    const int blk  = bid & 3;
    const int tid  = threadIdx.x;
    const int q    = tid & 7;            // dp quad: dp = 4q..4q+3
    const int chunk= tid >> 3;           // 0..31
    const int dd   = q >> 1;             // output dim (uniform across the quad)
    const int t0g  = blk * BLK_T + chunk * LT;   // global t start of this chunk

    __shared__ float s_am[BLK_T * DD];   // 4 KB  amul slice for this block
    __shared__ float sB[NCH][DPW];       // 4 KB  per-chunk local end values
    __shared__ float sA[NCH][DD];        // per-chunk amul products
    __shared__ float sQ[NCH][DD];        // exclusive prefix products of sA
    __shared__ float sAr[DD];            // block-range amul product
    __shared__ float sC[NCH][DPW];       // 4 KB  in-block exclusive carries
    __shared__ float sCin[DPW];          // incoming carry from predecessor

    // amul slice: BLK_T*DD = 1024 floats = 256 float4, one per thread
    ((float4*)s_am)[tid] = ((const float4*)g_amul)[blk * (BLK_T * DD / 4) + tid];
    __syncthreads();

    const float4* tbl_sw = (const float4*)g_sw;
    const float4* tbl_mn = (const float4*)g_mean;

    const size_t base = ((size_t)(s * TT + t0g) << 3) + q;   // float4 index

    // ---- Phase A: stream noise, write lp, z[8] in regs, chunk summary b ----
    float4 z[LT];
    float4 b = make_float4(0.f, 0.f, 0.f, 0.f);

#pragma unroll
    for (int i = 0; i < LT; i++) {
        const int ti = ((t0g + i) << 3) + q;          // table float4 index
        const int tl = (chunk << 3) + i;              // block-local t
        const float4 n  = noise4[base + (size_t)i * 8];
        const float4 sw = tbl_sw[ti];
        const float4 mn = tbl_mn[ti];
        if (write_lp) {
            float4 lp;
            lp.x = fmaf(-0.5f * n.x, n.x, -__logf(sw.x) - HLOG2PI);
            lp.y = fmaf(-0.5f * n.y, n.y, -__logf(sw.y) - HLOG2PI);
            lp.z = fmaf(-0.5f * n.z, n.z, -__logf(sw.z) - HLOG2PI);
            lp.w = fmaf(-0.5f * n.w, n.w, -__logf(sw.w) - HLOG2PI);
            __stcs(&lp4[base + (size_t)i * 8], lp);
        }
        float4 zz;
        zz.x = fmaf(sw.x, n.x, mn.x);
        zz.y = fmaf(sw.y, n.y, mn.y);
        zz.z = fmaf(sw.z, n.z, mn.z);
        zz.w = fmaf(sw.w, n.w, mn.w);
        z[i] = zz;
        const float am = s_am[(tl << 2) + dd];
        b.x = fmaf(am, b.x, zz.x);
        b.y = fmaf(am, b.y, zz.y);
        b.z = fmaf(am, b.z, zz.z);
        b.w = fmaf(am, b.w, zz.w);
    }
    ((float4*)sB[chunk])[q] = b;

    // ---- Phase B: per-chunk amul products (128 threads, 8 muls each) ----
    if (tid < NCH * DD) {
        const int c  = tid >> 2;
        const int d2 = tid & 3;
        float a = 1.0f;
#pragma unroll
        for (int i = 0; i < LT; i++)
            a *= s_am[(((c << 3) + i) << 2) + d2];
        sA[c][d2] = a;
    }
    __syncthreads();

    // ---- Phase C: in-block scans (warp0: carry chain; warp1[0:4]: Q chain) ----
    float bT = 0.0f;                     // block-total local carry (warp0 regs)
    if (tid < 32) {
        const int dp = tid;
        const int d2 = dp >> 3;
        float carry = 0.0f;
#pragma unroll
        for (int c = 0; c < NCH; c++) {
            sC[c][dp] = carry;
            carry = fmaf(sA[c][d2], carry, sB[c][dp]);
        }
        bT = carry;
    } else if (tid < 36) {
        const int d2 = tid - 32;
        float Qr = 1.0f;
#pragma unroll
        for (int c = 0; c < NCH; c++) {
            sQ[c][d2] = Qr;
            Qr *= sA[c][d2];
        }
        sAr[d2] = Qr;
    }
    __syncthreads();

    // ---- Lookback + publish (warp 0) ----
    if (tid < 32) {
        float cin = 0.0f;
        if (blk > 0) {
            if (tid == 0) {
                while (g_flag[bid - 1] == 0) { }     // predecessor has lower bid
            }
            __syncwarp();
            __threadfence();
            cin = __ldcg(&g_P[bid - 1][tid]);
        }
        sCin[tid] = cin;
        g_P[bid][tid] = fmaf(sAr[tid >> 3], cin, bT);   // inclusive carry
        __threadfence();
        __syncwarp();
        if (tid == 0) g_flag[bid] = 1;
    }
    __syncthreads();

    // ---- Phase D: replay recursion from registers with global carry ----
    const float  Qc = sQ[chunk][dd];
    const float4 c4 = ((const float4*)sCin)[q];
    float4 pv = ((const float4*)sC[chunk])[q];
    pv.x = fmaf(Qc, c4.x, pv.x);
    pv.y = fmaf(Qc, c4.y, pv.y);
    pv.z = fmaf(Qc, c4.z, pv.z);
    pv.w = fmaf(Qc, c4.w, pv.w);
#pragma unroll
    for (int i = 0; i < LT; i++) {
        const int tl = (chunk << 3) + i;
        const float am = s_am[(tl << 2) + dd];
        pv.x = fmaf(am, pv.x, z[i].x);
        pv.y = fmaf(am, pv.y, z[i].y);
        pv.z = fmaf(am, pv.z, z[i].z);
        pv.w = fmaf(am, pv.w, z[i].w);
        __stcs(&param4[base + (size_t)i * 8], pv);
    }
}

// ---------------------------------------------------------------------------
// Launch.  Inputs: 0:y 1:age 2:m 3:s_raw 4:a_raw 5:noise 6:cond_sample
//                  7:dim_idx 8:compute_log_prob
// Output: param (S,T,D,P) then log_prob (S,T,D,P), float32.
// ---------------------------------------------------------------------------
extern "C" void kernel_launch(void* const* d_in, const int* in_sizes, int n_in,
                              void* d_out, int out_size)
{
    const float* m      = (const float*)d_in[2];
    const float* s_raw  = (const float*)d_in[3];
    const float* a_raw  = (const float*)d_in[4];
    const float* noise  = (const float*)d_in[5];
    const int*   dimidx = (const int*)  d_in[7];

    float* out_param = (float*)d_out;
    int write_lp = (out_size >= (int)(2 * SZ)) ? 1 : 0;
    float* out_lp = out_param + SZ;

    const float4* noise4 = (const float4*)noise;
    float4* param4 = (float4*)out_param;
    float4* lp4    = (float4*)(write_lp ? out_lp : out_param);

    arma_precompute<<<128, 256>>>(m, s_raw, a_raw, dimidx);
    arma_main<<<NBLK, 256>>>(noise4, param4, lp4, write_lp);
}

// round 9
// speedup vs baseline: 1.0406x; 1.0406x over previous
#include <cuda_runtime.h>
#include <cuda_bf16.h>
#include <math.h>

// Problem constants
#define TT     1024
#define DD     4
#define PP     8
#define DPW    32                    // D*P
#define SS     256                   // N * N_SAMPLE
#define LT     4                     // timesteps per thread-chunk
#define NCH    128                   // chunks per block (128*4 = 512 t)
#define HALF_T 512                   // timesteps per block
#define NBLK   (SS*2)                // 512 blocks (sample, half)
#define TBL    (TT*DPW)              // 32768 table elements
#define SZ     ((size_t)SS*TT*DPW)   // 8388608 elements per output tensor
#define HLOG2PI 0.91893853320467274178f

// Precomputed tables + cross-half handoff (allocation-free scratch)
__device__ float g_mean[TBL];
__device__ float g_sw[TBL];
__device__ float g_amul[TT*DD];          // sigmoid(a_raw[t-1,d]), amul[0,*]=0
__device__ volatile int g_flag[SS];      // half0-done flags
__device__ float g_P[SS][DPW];           // half0 inclusive carry per sample

// ---------------------------------------------------------------------------
// K0: precompute tables AND reset handoff flags (same stream -> ordered).
// ---------------------------------------------------------------------------
__global__ void arma_precompute(const float* __restrict__ m,
                                const float* __restrict__ s_raw,
                                const float* __restrict__ a_raw,
                                const int*   __restrict__ dim_idx)
{
    int idx = blockIdx.x * blockDim.x + threadIdx.x;
    if (idx >= TBL) return;
    if (idx < SS) g_flag[idx] = 0;

    int t  = idx >> 5;
    int dp = idx & 31;
    int dd = dp >> 3;
    int p  = dp & 7;
    int src = dim_idx[dd];

    float am = 0.0f;
    if (t > 0) {
        float x = a_raw[(t - 1) * DD + src];
        am = 1.0f / (1.0f + __expf(-x));
    }

    float sv = s_raw[t * DPW + src * PP + p];
    float sw = (sv > 20.0f) ? sv : __logf(1.0f + __expf(sv));   // softplus
    float mn = (1.0f - am) * m[t * DPW + src * PP + p];

    g_mean[idx] = mn;
    g_sw[idx]   = sw;
    if (p == 0) g_amul[t * DD + dd] = am;
}

// ---------------------------------------------------------------------------
// Main kernel: block = (sample, half). 1024 threads = 128 chunks(4t) x 8 quads.
// No z[] register array: Phase A stores within-chunk LOCAL scan values into
// param (plain store, stays in L2); Phase D re-reads them (L2 hit) and adds
// Qstep * (in-half carry + cross-half carry). ~30 regs -> 2 blocks/SM = 100%
// occupancy. Cross-half carry: depth-1 flag handoff (adjacent bids).
// ---------------------------------------------------------------------------
__global__ void __launch_bounds__(1024, 2)
arma_main(const float4* __restrict__ noise4,
          float4* __restrict__ param4,
          float4* __restrict__ lp4,
          int write_lp)
{
    const int bid   = blockIdx.x;
    const int s     = bid >> 1;
    const int half  = bid & 1;
    const int tid   = threadIdx.x;
    const int q     = tid & 7;            // dp quad: dp = 4q..4q+3
    const int chunk = tid >> 3;           // 0..127  (1024 thr / 8 quads)
    const int dd    = q >> 1;             // output dim (uniform in quad)
    const int t0    = half * HALF_T + (chunk << 2);   // global t of chunk start

    __shared__ float s_am[HALF_T * DD];   // 8 KB   amul slice for this half
    __shared__ float sB[NCH][DPW];        // 16 KB  per-chunk local end values
    __shared__ float sC[NCH][DPW];        // 16 KB  exclusive in-half carries
    __shared__ float sA[NCH][DD];         // 2 KB   per-chunk amul products
    __shared__ float sQ[NCH][DD];         // 2 KB   exclusive prefix products
    __shared__ float sCin[DPW];           // incoming cross-half carry

    // amul slice: HALF_T*DD = 2048 floats = 512 float4
    if (tid < 512)
        ((float4*)s_am)[tid] = ((const float4*)g_amul)[half * (HALF_T * DD / 4) + tid];
    __syncthreads();

    const float4* tbl_sw = (const float4*)g_sw;
    const float4* tbl_mn = (const float4*)g_mean;

    const size_t base = ((size_t)(s * TT + t0) << 3) + q;   // float4 index

    // ---- Phase A: stream noise, write lp, store within-chunk locals ----
    float4 loc = make_float4(0.f, 0.f, 0.f, 0.f);

#pragma unroll
    for (int i = 0; i < LT; i++) {
        const int ti = ((t0 + i) << 3) + q;           // table float4 index
        const int tl = (chunk << 2) + i;              // block-local t
        const float4 n  = __ldcs(&noise4[base + (size_t)i * 8]);
        const float4 sw = tbl_sw[ti];
        const float4 mn = tbl_mn[ti];
        if (write_lp) {
            float4 lp;
            lp.x = fmaf(-0.5f * n.x, n.x, -__logf(sw.x) - HLOG2PI);
            lp.y = fmaf(-0.5f * n.y, n.y, -__logf(sw.y) - HLOG2PI);
            lp.z = fmaf(-0.5f * n.z, n.z, -__logf(sw.z) - HLOG2PI);
            lp.w = fmaf(-0.5f * n.w, n.w, -__logf(sw.w) - HLOG2PI);
            __stcs(&lp4[base + (size_t)i * 8], lp);
        }
        const float am = s_am[(tl << 2) + dd];
        loc.x = fmaf(am, loc.x, fmaf(sw.x, n.x, mn.x));
        loc.y = fmaf(am, loc.y, fmaf(sw.y, n.y, mn.y));
        loc.z = fmaf(am, loc.z, fmaf(sw.z, n.z, mn.z));
        loc.w = fmaf(am, loc.w, fmaf(sw.w, n.w, mn.w));
        param4[base + (size_t)i * 8] = loc;   // local value; default policy (L2)
    }
    ((float4*)sB[chunk])[q] = loc;            // chunk-end local value

    // ---- Phase B: per-chunk amul products (512 threads, one (c,d2) each) ----
    if (tid < NCH * DD) {
        const int c  = tid >> 2;              // 0..127
        const int d2 = tid & 3;
        float a = 1.0f;
#pragma unroll
        for (int i = 0; i < LT; i++)
            a *= s_am[(((c << 2) + i) << 2) + d2];
        sA[c][d2] = a;
    }
    __syncthreads();

    // ---- Phase C: scans + cross-half handoff ----
    if (tid < 32) {
        const int dp = tid;
        const int d2 = dp >> 3;
        float carry = 0.0f;
#pragma unroll
        for (int c = 0; c < NCH; c++) {
            sC[c][dp] = carry;
            carry = fmaf(sA[c][d2], carry, sB[c][dp]);
        }
        if (half == 0) {
            sCin[dp] = 0.0f;
            g_P[s][dp] = carry;               // half0 inclusive total
            __threadfence();
            __syncwarp();
            if (dp == 0) g_flag[s] = 1;
        } else {
            if (dp == 0) {
                while (g_flag[s] == 0) { }    // predecessor bid = bid-1
            }
            __syncwarp();
            __threadfence();
            sCin[dp] = __ldcg(&g_P[s][dp]);
        }
    } else if (tid < 36) {
        const int d2 = tid - 32;
        float Qr = 1.0f;
#pragma unroll
        for (int c = 0; c < NCH; c++) {
            sQ[c][d2] = Qr;
            Qr *= sA[c][d2];
        }
    }
    __syncthreads();

    // ---- Phase D: final = local + Qstep * (sC + sQ*cin); locals from L2 ----
    const float4 c4 = ((const float4*)sCin)[q];
    float4 cv = ((const float4*)sC[chunk])[q];
    const float Qc = sQ[chunk][dd];
    cv.x = fmaf(Qc, c4.x, cv.x);              // state entering this chunk
    cv.y = fmaf(Qc, c4.y, cv.y);
    cv.z = fmaf(Qc, c4.z, cv.z);
    cv.w = fmaf(Qc, c4.w, cv.w);
    float Qs = 1.0f;
#pragma unroll
    for (int i = 0; i < LT; i++) {
        const int tl = (chunk << 2) + i;
        const float am = s_am[(tl << 2) + dd];
        Qs *= am;
        const float4 lv = param4[base + (size_t)i * 8];   // L2 hit (own write)
        float4 outv;
        outv.x = fmaf(Qs, cv.x, lv.x);
        outv.y = fmaf(Qs, cv.y, lv.y);
        outv.z = fmaf(Qs, cv.z, lv.z);
        outv.w = fmaf(Qs, cv.w, lv.w);
        __stcs(&param4[base + (size_t)i * 8], outv);
    }
}

// ---------------------------------------------------------------------------
// Launch.  Inputs: 0:y 1:age 2:m 3:s_raw 4:a_raw 5:noise 6:cond_sample
//                  7:dim_idx 8:compute_log_prob
// Output: param (S,T,D,P) then log_prob (S,T,D,P), float32.
// ---------------------------------------------------------------------------
extern "C" void kernel_launch(void* const* d_in, const int* in_sizes, int n_in,
                              void* d_out, int out_size)
{
    const float* m      = (const float*)d_in[2];
    const float* s_raw  = (const float*)d_in[3];
    const float* a_raw  = (const float*)d_in[4];
    const float* noise  = (const float*)d_in[5];
    const int*   dimidx = (const int*)  d_in[7];

    float* out_param = (float*)d_out;
    int write_lp = (out_size >= (int)(2 * SZ)) ? 1 : 0;
    float* out_lp = out_param + SZ;

    const float4* noise4 = (const float4*)noise;
    float4* param4 = (float4*)out_param;
    float4* lp4    = (float4*)(write_lp ? out_lp : out_param);

    arma_precompute<<<128, 256>>>(m, s_raw, a_raw, dimidx);
    arma_main<<<NBLK, 1024>>>(noise4, param4, lp4, write_lp);
}

// round 10
// speedup vs baseline: 1.4061x; 1.3513x over previous
#include <cuda_runtime.h>
#include <cuda_bf16.h>
#include <math.h>

// Problem constants
#define TT     1024
#define DD     4
#define PP     8
#define DPW    32                    // D*P
#define SS     256                   // N * N_SAMPLE
#define LT     16                    // timesteps per chunk
#define NCHUNK 64                    // chunks along T (64*16 = 1024)
#define TBL    (TT*DPW)              // 32768 table elements
#define SZ     ((size_t)SS*TT*DPW)   // 8388608 elements per output tensor
#define HLOG2PI 0.91893853320467274178f

// Scratch (static __device__ arrays — allocation-free)
__device__ float  g_mean[TBL];
__device__ float  g_sw[TBL];
__device__ float  g_amul[TT*DD];          // sigmoid(a_raw[t-1,d]), amul[0,*]=0
__device__ float4 g_B[SS*NCHUNK*8];       // per-chunk local end values, 2 MB
__device__ float4 g_C[SS*NCHUNK*8];       // exclusive carries, 2 MB

// ---------------------------------------------------------------------------
// K0: precompute per-(t,dp) tables. Fast-math; tiny.
// ---------------------------------------------------------------------------
__global__ void arma_precompute(const float* __restrict__ m,
                                const float* __restrict__ s_raw,
                                const float* __restrict__ a_raw,
                                const int*   __restrict__ dim_idx)
{
    int idx = blockIdx.x * blockDim.x + threadIdx.x;
    if (idx >= TBL) return;
    int t  = idx >> 5;
    int dp = idx & 31;
    int dd = dp >> 3;
    int p  = dp & 7;
    int src = dim_idx[dd];

    float am = 0.0f;
    if (t > 0) {
        float x = a_raw[(t - 1) * DD + src];
        am = 1.0f / (1.0f + __expf(-x));
    }

    float sv = s_raw[t * DPW + src * PP + p];
    float sw = (sv > 20.0f) ? sv : __logf(1.0f + __expf(sv));   // softplus
    float mn = (1.0f - am) * m[t * DPW + src * PP + p];

    g_mean[idx] = mn;
    g_sw[idx]   = sw;
    if (p == 0) g_amul[t * DD + dd] = am;
}

// ---------------------------------------------------------------------------
// P1: stream noise once (float4, DEFAULT policy so L2 retains it for P3),
// write lp (__stcs, never re-read), emit per-chunk summaries b.
// Grid: 512 blocks (s, half) x 256 threads (32 chunks x 8 quads). LT=16 gives
// deep per-thread MLP -> this pass runs at DRAM bandwidth (R2-measured).
// ---------------------------------------------------------------------------
__global__ void __launch_bounds__(256)
arma_pass1(const float4* __restrict__ noise4,
           float4* __restrict__ lp4,
           int write_lp)
{
    const int s     = blockIdx.x >> 1;
    const int half  = blockIdx.x & 1;
    const int q     = threadIdx.x & 7;            // dp quad: dp = 4q..4q+3
    const int chunk = (half << 5) + (threadIdx.x >> 3);
    const int dd    = q >> 1;
    const int t0    = chunk << 4;

    const float4* tbl_sw = (const float4*)g_sw;
    const float4* tbl_mn = (const float4*)g_mean;

    const size_t base = ((size_t)((s << 10) + t0) << 3) + q;   // float4 index

    float4 b = make_float4(0.f, 0.f, 0.f, 0.f);

#pragma unroll
    for (int i = 0; i < LT; i++) {
        const int t  = t0 + i;
        const int ti = (t << 3) + q;
        const float4 n = noise4[base + (size_t)i * 8];         // keep in L2
        const float4 sw = tbl_sw[ti];
        const float4 mn = tbl_mn[ti];
        if (write_lp) {
            float4 lp;
            lp.x = fmaf(-0.5f * n.x, n.x, -__logf(sw.x) - HLOG2PI);
            lp.y = fmaf(-0.5f * n.y, n.y, -__logf(sw.y) - HLOG2PI);
            lp.z = fmaf(-0.5f * n.z, n.z, -__logf(sw.z) - HLOG2PI);
            lp.w = fmaf(-0.5f * n.w, n.w, -__logf(sw.w) - HLOG2PI);
            __stcs(&lp4[base + (size_t)i * 8], lp);
        }
        const float am = g_amul[(t << 2) + dd];
        b.x = fmaf(am, b.x, fmaf(sw.x, n.x, mn.x));
        b.y = fmaf(am, b.y, fmaf(sw.y, n.y, mn.y));
        b.z = fmaf(am, b.z, fmaf(sw.z, n.z, mn.z));
        b.w = fmaf(am, b.w, fmaf(sw.w, n.w, mn.w));
    }
    g_B[(((size_t)s << 6) + chunk) * 8 + q] = b;
}

// ---------------------------------------------------------------------------
// P2: per-sample scan, entirely in shared memory (this was 32us in gmem).
// One 256-thread block per sample: load amul (16KB) + summaries B (8KB) into
// smem, compute per-chunk products sA in-block, warp0 runs the 64-step fma
// carry chain (~300 cyc), coalesced scalar writeback of carries.
// ---------------------------------------------------------------------------
__global__ void __launch_bounds__(256)
arma_scan()
{
    const int s   = blockIdx.x;
    const int tid = threadIdx.x;

    __shared__ float s_am[TT * DD];       // 16 KB
    __shared__ float sA[NCHUNK][DD];      // 1 KB
    __shared__ float sB[NCHUNK][DPW];     // 8 KB

    // Load amul: 4096 floats = 1024 float4, 4 per thread
#pragma unroll
    for (int k = 0; k < 4; k++)
        ((float4*)s_am)[tid + 256 * k] = ((const float4*)g_amul)[tid + 256 * k];

    // Load B: 512 float4, 2 per thread
    const float4* Bs = g_B + ((size_t)s << 6) * 8;
    ((float4*)sB)[tid]       = Bs[tid];
    ((float4*)sB)[tid + 256] = Bs[tid + 256];
    __syncthreads();

    // Per-chunk amul products: one (chunk, d) per thread
    {
        const int c  = tid >> 2;
        const int d2 = tid & 3;
        float a = 1.0f;
#pragma unroll
        for (int i = 0; i < LT; i++)
            a *= s_am[(((c << 4) + i) << 2) + d2];
        sA[c][d2] = a;
    }
    __syncthreads();

    // Warp0: serial affine scan over 64 chunks, one dp chain per lane.
    if (tid < 32) {
        const int dp = tid;
        const int d2 = dp >> 3;
        float* Cf = (float*)g_C + ((size_t)s << 6) * 32;
        float carry = 0.0f;
#pragma unroll
        for (int c = 0; c < NCHUNK; c++) {
            Cf[c * 32 + dp] = carry;                       // coalesced 128B
            carry = fmaf(sA[c][d2], carry, sB[c][dp]);
        }
    }
}

// ---------------------------------------------------------------------------
// P3: replay recursion with correct carries; noise re-read is an L2 hit.
// Same geometry as P1.
// ---------------------------------------------------------------------------
__global__ void __launch_bounds__(256)
arma_pass2(const float4* __restrict__ noise4,
           float4* __restrict__ param4)
{
    const int s     = blockIdx.x >> 1;
    const int half  = blockIdx.x & 1;
    const int q     = threadIdx.x & 7;
    const int chunk = (half << 5) + (threadIdx.x >> 3);
    const int dd    = q >> 1;
    const int t0    = chunk << 4;

    const float4* tbl_sw = (const float4*)g_sw;
    const float4* tbl_mn = (const float4*)g_mean;

    const size_t base = ((size_t)((s << 10) + t0) << 3) + q;

    float4 pv = g_C[(((size_t)s << 6) + chunk) * 8 + q];

#pragma unroll
    for (int i = 0; i < LT; i++) {
        const int t  = t0 + i;
        const int ti = (t << 3) + q;
        const float4 n  = noise4[base + (size_t)i * 8];   // L2 hit (read in P1)
        const float4 sw = tbl_sw[ti];
        const float4 mn = tbl_mn[ti];
        const float am  = g_amul[(t << 2) + dd];
        pv.x = fmaf(am, pv.x, fmaf(sw.x, n.x, mn.x));
        pv.y = fmaf(am, pv.y, fmaf(sw.y, n.y, mn.y));
        pv.z = fmaf(am, pv.z, fmaf(sw.z, n.z, mn.z));
        pv.w = fmaf(am, pv.w, fmaf(sw.w, n.w, mn.w));
        __stcs(&param4[base + (size_t)i * 8], pv);
    }
}

// ---------------------------------------------------------------------------
// Launch.  Inputs: 0:y 1:age 2:m 3:s_raw 4:a_raw 5:noise 6:cond_sample
//                  7:dim_idx 8:compute_log_prob
// Output: param (S,T,D,P) then log_prob (S,T,D,P), float32.
// ---------------------------------------------------------------------------
extern "C" void kernel_launch(void* const* d_in, const int* in_sizes, int n_in,
                              void* d_out, int out_size)
{
    const float* m      = (const float*)d_in[2];
    const float* s_raw  = (const float*)d_in[3];
    const float* a_raw  = (const float*)d_in[4];
    const float* noise  = (const float*)d_in[5];
    const int*   dimidx = (const int*)  d_in[7];

    float* out_param = (float*)d_out;
    int write_lp = (out_size >= (int)(2 * SZ)) ? 1 : 0;
    float* out_lp = out_param + SZ;

    const float4* noise4 = (const float4*)noise;
    float4* param4 = (float4*)out_param;
    float4* lp4    = (float4*)(write_lp ? out_lp : out_param);

    arma_precompute<<<256, 128>>>(m, s_raw, a_raw, dimidx);
    arma_pass1<<<SS * 2, 256>>>(noise4, lp4, write_lp);
    arma_scan<<<SS, 256>>>();
    arma_pass2<<<SS * 2, 256>>>(noise4, param4);
}